// round 15
// baseline (speedup 1.0000x reference)
#include <cuda_runtime.h>
#include <math.h>
#include <stdint.h>

// Problem constants:
//   X: [16384, 1024] fp32; per layer: wpn [2048,2048], b [2048], a [1024,9,1]
//   scale [1], out_bias [1024]; out [16384,1024] fp32
#define NROWS 16384
#define INW   1024
#define OUTW  2048
#define NG    1024

#define BM 128
#define BN 128
#define BK 128                 // int8 elements per chunk (128 bytes/row)
#define NCHUNK (INW / BK)      // 8
#define NTHREADS 256

// SMEM stage: A (128x128 s8 = 16KB) + B (128x128 s8 = 16KB)
#define OFF_A  0
#define OFF_B  16384
#define STAGE  32768
#define NSTAGE 3
#define SMEM_TOTAL (NSTAGE * STAGE)   // 98304 -> 2 CTAs/SM

// epilogue staging: [128 rows][64 cols] int8, stride 80 (16B-aligned, conflict-free)
#define STG_STRIDE 80

// -------- static device buffers (no allocation) --------
__device__ int8_t g_A0[(size_t)NROWS * INW];
__device__ int8_t g_A1[(size_t)NROWS * INW];
__device__ int8_t g_B[3][(size_t)OUTW * INW];
__device__ float  g_wscale[3][OUTW];   // per-output-channel |raw_w| max
__device__ float  g_ascale[NROWS];     // per-row |X| max

// -------- PTX helpers (legal on compute_100) --------
__device__ __forceinline__ uint32_t smem_u32(const void* p) {
    uint32_t a;
    asm("{ .reg .u64 t; cvta.to.shared.u64 t, %1; cvt.u32.u64 %0, t; }" : "=r"(a) : "l"(p));
    return a;
}
#define CP_ASYNC16(dst, src) \
    asm volatile("cp.async.cg.shared.global [%0], [%1], 16;" :: "r"(dst), "l"(src))
#define CP_COMMIT() asm volatile("cp.async.commit_group;" ::: "memory")
#define CP_WAIT1()  asm volatile("cp.async.wait_group 1;" ::: "memory")
#define CP_WAIT0()  asm volatile("cp.async.wait_group 0;" ::: "memory")

#define LDSM4(r0, r1, r2, r3, addr) \
    asm volatile("ldmatrix.sync.aligned.m8n8.x4.shared.b16 {%0,%1,%2,%3}, [%4];" \
                 : "=r"(r0), "=r"(r1), "=r"(r2), "=r"(r3) : "r"(addr))

#define MMA_S8(d, a, b0, b1) \
    asm volatile("mma.sync.aligned.m16n8k32.row.col.s32.s8.s8.s32 " \
                 "{%0,%1,%2,%3},{%4,%5,%6,%7},{%8,%9},{%0,%1,%2,%3};" \
                 : "+r"((d)[0]), "+r"((d)[1]), "+r"((d)[2]), "+r"((d)[3]) \
                 : "r"((a)[0]), "r"((a)[1]), "r"((a)[2]), "r"((a)[3]), "r"(b0), "r"(b1))

__device__ __forceinline__ int q8(float v, float qs) {
    int q = __float2int_rn(v * qs);
    return max(-127, min(127, q));
}

// -------- fused prep kernels (single pass, localized scales) --------

// One warp per row: row absmax + quantize in one read. 8 rows/CTA.
__global__ void prep_x(const float* __restrict__ X, int8_t* __restrict__ A,
                       float* __restrict__ ascale)
{
    const int row  = blockIdx.x * 8 + (threadIdx.x >> 5);
    const int lane = threadIdx.x & 31;
    const float* xr = X + (size_t)row * INW;

    // lane owns floats [lane*16, +16) and [512 + lane*16, +16)
    float4 v[8];
    #pragma unroll
    for (int q = 0; q < 4; q++) v[q]     = *(const float4*)(xr + lane * 16 + q * 4);
    #pragma unroll
    for (int q = 0; q < 4; q++) v[4 + q] = *(const float4*)(xr + 512 + lane * 16 + q * 4);

    float m = 0.f;
    #pragma unroll
    for (int q = 0; q < 8; q++)
        m = fmaxf(m, fmaxf(fmaxf(fabsf(v[q].x), fabsf(v[q].y)),
                           fmaxf(fabsf(v[q].z), fabsf(v[q].w))));
    #pragma unroll
    for (int o = 16; o > 0; o >>= 1) m = fmaxf(m, __shfl_xor_sync(0xFFFFFFFF, m, o));
    const float rm = fmaxf(m, 1e-20f);
    const float qs = 127.f / rm;

    uint32_t pk[8];
    #pragma unroll
    for (int q = 0; q < 8; q++)
        pk[q] = (uint32_t)(q8(v[q].x, qs) & 0xFF)
              | ((uint32_t)(q8(v[q].y, qs) & 0xFF) << 8)
              | ((uint32_t)(q8(v[q].z, qs) & 0xFF) << 16)
              | ((uint32_t)(q8(v[q].w, qs) & 0xFF) << 24);
    int8_t* ar = A + (size_t)row * INW;
    *(uint4*)(ar + lane * 16)       = make_uint4(pk[0], pk[1], pk[2], pk[3]);
    *(uint4*)(ar + 512 + lane * 16) = make_uint4(pk[4], pk[5], pk[6], pk[7]);
    if (lane == 0) ascale[row] = rm;
}

// CTA owns 32 n-columns x full k. Phase 1: per-channel absmax (DRAM stream).
// Phase 2: re-read (L2-hot), quantize, transpose to Bt[n][k], full-row stores.
__global__ void prep_wf(const float* __restrict__ w0p, const float* __restrict__ w1p,
                        const float* __restrict__ w2p, int8_t* __restrict__ Bbase,
                        float* __restrict__ wsbase)
{
    __shared__ float s[128][33];
    __shared__ float red[8][32];
    __shared__ float wss[32];
    const int layer = blockIdx.y;
    const float* wpn = (layer == 0) ? w0p : (layer == 1) ? w1p : w2p;
    int8_t* B = Bbase + (size_t)layer * OUTW * INW;
    float* ws = wsbase + (size_t)layer * OUTW;
    const int n0 = blockIdx.x * 32;
    const int t = threadIdx.x;          // 256
    const int nl = t & 31, kk = t >> 5; // 32 n x 8 k-lanes

    // phase 1: per-channel absmax
    float m = 0.f;
    for (int k = kk; k < INW; k += 8) {
        float d = wpn[(size_t)k * OUTW + n0 + nl] - wpn[(size_t)(k + INW) * OUTW + n0 + nl];
        m = fmaxf(m, fabsf(d));
    }
    red[kk][nl] = m;
    __syncthreads();
    if (t < 32) {
        float mm = red[0][t];
        #pragma unroll
        for (int i = 1; i < 8; i++) mm = fmaxf(mm, red[i][t]);
        mm = fmaxf(mm, 1e-20f);
        wss[t] = 127.f / mm;
        ws[n0 + t] = mm;
    }
    __syncthreads();

    // phase 2: quantize + transpose, 128-k tiles
    for (int kt = 0; kt < INW; kt += 128) {
        #pragma unroll
        for (int i = 0; i < 16; i++) {
            int k = kt + kk + i * 8;
            s[kk + i * 8][nl] = wpn[(size_t)k * OUTW + n0 + nl]
                              - wpn[(size_t)(k + INW) * OUTW + n0 + nl];
        }
        __syncthreads();
        const int n = t >> 3, seg = t & 7;
        const float qs = wss[n];
        uint32_t pk[4];
        #pragma unroll
        for (int q = 0; q < 4; q++) {
            uint32_t v = 0;
            #pragma unroll
            for (int j = 0; j < 4; j++)
                v |= (uint32_t)(q8(s[seg * 16 + q * 4 + j][n], qs) & 0xFF) << (8 * j);
            pk[q] = v;
        }
        *(uint4*)(B + (size_t)(n0 + n) * INW + kt + seg * 16) = make_uint4(pk[0], pk[1], pk[2], pk[3]);
        __syncthreads();
    }
}

// -------- fused GEMM(int8, mma.sync) + activation --------
__device__ __forceinline__ void compute_stage(
    uint32_t stA, uint32_t stB,
    int lane, int warp_m, int warp_n, int acc[4][4][4])
{
    const uint32_t swx  = (uint32_t)(lane & 7) * 16;
    const uint32_t rsel = (uint32_t)(lane & 15);
    const uint32_t csel = (uint32_t)(lane >> 4) * 16;
    #pragma unroll
    for (int ks = 0; ks < 4; ks++) {
        const uint32_t col = ((uint32_t)ks * 32 + csel) ^ swx;
        uint32_t bh[2][4];
        #pragma unroll
        for (int pb = 0; pb < 2; pb++) {
            uint32_t ro = (uint32_t)(warp_n + pb * 16 + rsel) * 128 + col;
            LDSM4(bh[pb][0], bh[pb][1], bh[pb][2], bh[pb][3], stB + ro);
        }
        uint32_t afr[2][4];
        {
            uint32_t ro = (uint32_t)(warp_m + rsel) * 128 + col;
            LDSM4(afr[0][0], afr[0][1], afr[0][2], afr[0][3], stA + ro);
        }
        #pragma unroll
        for (int mb = 0; mb < 4; mb++) {
            const int cur = mb & 1, nxt = cur ^ 1;
            if (mb < 3) {
                uint32_t ro = (uint32_t)(warp_m + (mb + 1) * 16 + rsel) * 128 + col;
                LDSM4(afr[nxt][0], afr[nxt][1], afr[nxt][2], afr[nxt][3], stA + ro);
            }
            #pragma unroll
            for (int nb = 0; nb < 4; nb++) {
                const int pb = nb >> 1, s = nb & 1;
                MMA_S8(acc[mb][nb], afr[cur], bh[pb][s], bh[pb][s + 2]);
            }
        }
    }
}

__device__ __forceinline__ float act_eval(float x0, float x1, const float* __restrict__ av)
{
    x0 = fminf(fmaxf(x0, -1.f), 1.f);
    x1 = fminf(fmaxf(x1, -1.f), 1.f);
    const float lo0 = (x0 < 0.f) ? -1.f : 0.f;
    const float lo1 = (x1 < 0.f) ? -1.f : 0.f;
    const float f0 = x0 - lo0;
    const float f1 = x1 - lo1;
    const int base = ((x0 < 0.f) ? 0 : 1) + 3 * ((x1 < 0.f) ? 0 : 1);
    const float v00 = __ldg(av + base);
    const float v10 = __ldg(av + base + 1);
    const float v01 = __ldg(av + base + 3);
    const float v11 = __ldg(av + base + 4);
    return (1.f - f0) * ((1.f - f1) * v00 + f1 * v01)
         +        f0  * ((1.f - f1) * v10 + f1 * v11);
}

template<int LAST, int FIRST>
__global__ void __launch_bounds__(NTHREADS, 2)
gemm_act(const int8_t* __restrict__ A, const int8_t* __restrict__ B,
         const float* __restrict__ wscale, const float* __restrict__ ascale,
         const float* __restrict__ bias, const float* __restrict__ act,
         const float* __restrict__ scale_p, const float* __restrict__ out_bias,
         int8_t* __restrict__ Ynext, float* __restrict__ Yout)
{
    extern __shared__ __align__(1024) char smem[];
    const uint32_t sb = smem_u32(smem);
    const int tid  = threadIdx.x;
    const int wid  = tid >> 5;
    const int lane = tid & 31;
    const int rowBase = blockIdx.y * BM;
    const int nBase   = blockIdx.x * BN;
    const int warp_m = (wid & 1) * 64;        // {0, 64}
    const int warp_n = (wid >> 1) * 32;       // {0, 32, 64, 96}

    // ---- loader mapping: 256 thr; r0 = tid>>3 in 0..31, 16B segment ----
    const int r0   = tid >> 3;
    const int cseg = (tid & 7) * 16;
    const uint32_t swc = (uint32_t)cseg ^ ((uint32_t)(r0 & 7) * 16);
    uint32_t swOff[4];
    #pragma unroll
    for (int i = 0; i < 4; i++)
        swOff[i] = (uint32_t)(r0 + 32 * i) * 128 + swc;

    const char* gA = (const char*)(A + (size_t)(rowBase + r0) * INW) + cseg;
    const char* gB = (const char*)(B + (size_t)(nBase  + r0) * INW) + cseg;
    const size_t RSTRIDE = (size_t)32 * INW;   // 32 rows (1 byte/elem)

    int acc[4][4][4];
    #pragma unroll
    for (int a = 0; a < 4; a++)
        #pragma unroll
        for (int b = 0; b < 4; b++)
            #pragma unroll
            for (int q = 0; q < 4; q++) acc[a][b][q] = 0;

    // prologue: stages 0..1
    #pragma unroll
    for (int p = 0; p < 2; p++) {
        const uint32_t st = sb + p * STAGE;
        const size_t go = (size_t)p * 128;   // BK bytes along k
        #pragma unroll
        for (int i = 0; i < 4; i++) {
            CP_ASYNC16(st + OFF_A + swOff[i], gA + go + i * RSTRIDE);
            CP_ASYNC16(st + OFF_B + swOff[i], gB + go + i * RSTRIDE);
        }
        CP_COMMIT();
    }

    for (int c = 0; c < NCHUNK; c++) {
        if (c + 1 < NCHUNK) CP_WAIT1();
        else                CP_WAIT0();
        __syncthreads();   // stage c resident; all warps done reading stage (c-1)%3

        if (c + 2 < NCHUNK) {
            const uint32_t st = sb + ((c + 2) % NSTAGE) * STAGE;
            const size_t go = (size_t)(c + 2) * 128;
            #pragma unroll
            for (int i = 0; i < 4; i++) {
                CP_ASYNC16(st + OFF_A + swOff[i], gA + go + i * RSTRIDE);
                CP_ASYNC16(st + OFF_B + swOff[i], gB + go + i * RSTRIDE);
            }
            CP_COMMIT();
        }
        const uint32_t st = sb + (c % NSTAGE) * STAGE;
        compute_stage(st + OFF_A, st + OFF_B, lane, warp_m, warp_n, acc);
    }

    // ---- epilogue: per-row x per-channel dequant + bias + grid activation ----
    const float ls = cbrtf(fabsf(scale_p[0]));
    const float inv127 = 1.f / 127.f;
    const float lsq = ls * inv127;            // per-unit A scale (mid layers)
    const int gWarp = ((nBase + warp_n) >> 1);
    const int glWarp = (warp_n >> 1);   // CTA-local group offset (0,16,32,48)

    #pragma unroll
    for (int mb = 0; mb < 4; mb++) {
        const int rl  = warp_m + mb * 16 + (lane >> 2);   // CTA-local row
        const int rlo = rowBase + rl;
        const float aLo = FIRST ? ascale[rlo]     * lsq : lsq;
        const float aHi = FIRST ? ascale[rlo + 8] * lsq : lsq;
        #pragma unroll
        for (int nb = 0; nb < 4; nb++) {
            const int g  = gWarp + nb * 4 + (lane & 3);
            const int c0 = 2 * g;
            const float2 wsv = *(const float2*)(wscale + c0);
            const float sB0 = wsv.x * inv127, sB1 = wsv.y * inv127;
            const float b0v = bias[c0], b1v = bias[c0 + 1];
            const float* av = act + (size_t)g * 9;
            const int* d = acc[mb][nb];
            const float oLo = act_eval((float)d[0] * aLo * sB0 + b0v,
                                       (float)d[1] * aLo * sB1 + b1v, av);
            const float oHi = act_eval((float)d[2] * aHi * sB0 + b0v,
                                       (float)d[3] * aHi * sB1 + b1v, av);
            if (LAST) {
                const float ob = out_bias[g];
                Yout[(size_t)rlo * NG + g]       = oLo + ob;
                Yout[(size_t)(rlo + 8) * NG + g] = oHi + ob;
            } else {
                // stage int8 result in SMEM (stage-0 buffer is dead past the last sync)
                const int gl = glWarp + nb * 4 + (lane & 3);
                smem[rl * STG_STRIDE + gl]       = (char)(int8_t)q8(oLo, 127.f);
                smem[(rl + 8) * STG_STRIDE + gl] = (char)(int8_t)q8(oHi, 127.f);
            }
        }
    }
    if (!LAST) {
        __syncthreads();
        // coalesced copy-out: 128 rows x 64 bytes; thread -> 32B of one row
        const int r = tid >> 1, half = tid & 1;
        const char* src = smem + r * STG_STRIDE + half * 32;
        uint4 v0 = *(const uint4*)src;
        uint4 v1 = *(const uint4*)(src + 16);
        int8_t* dst = Ynext + (size_t)(rowBase + r) * NG + (nBase >> 1) + half * 32;
        *(uint4*)dst        = v0;
        *(uint4*)(dst + 16) = v1;
    }
}

extern "C" void kernel_launch(void* const* d_in, const int* in_sizes, int n_in,
                              void* d_out, int out_size)
{
    (void)in_sizes; (void)n_in; (void)out_size;
    const float* X     = (const float*)d_in[0];
    const float* w0    = (const float*)d_in[1];
    const float* b0    = (const float*)d_in[2];
    const float* a0    = (const float*)d_in[3];
    const float* w1    = (const float*)d_in[4];
    const float* b1    = (const float*)d_in[5];
    const float* a1    = (const float*)d_in[6];
    const float* w2    = (const float*)d_in[7];
    const float* b2    = (const float*)d_in[8];
    const float* a2    = (const float*)d_in[9];
    const float* scale = (const float*)d_in[10];
    const float* outb  = (const float*)d_in[11];
    float* out = (float*)d_out;

    int8_t *A0, *A1, *B;
    float *WS, *AS;
    cudaGetSymbolAddress((void**)&A0, g_A0);
    cudaGetSymbolAddress((void**)&A1, g_A1);
    cudaGetSymbolAddress((void**)&B,  g_B);
    cudaGetSymbolAddress((void**)&WS, g_wscale);
    cudaGetSymbolAddress((void**)&AS, g_ascale);
    const size_t WSTRIDE = (size_t)OUTW * INW;

    cudaFuncSetAttribute(gemm_act<0,1>, cudaFuncAttributeMaxDynamicSharedMemorySize, SMEM_TOTAL);
    cudaFuncSetAttribute(gemm_act<0,0>, cudaFuncAttributeMaxDynamicSharedMemorySize, SMEM_TOTAL);
    cudaFuncSetAttribute(gemm_act<1,0>, cudaFuncAttributeMaxDynamicSharedMemorySize, SMEM_TOTAL);

    // fused prep (single pass each)
    prep_x<<<NROWS / 8, 256>>>(X, A0, AS);
    prep_wf<<<dim3(OUTW / 32, 3), 256>>>(w0, w1, w2, B, WS);

    dim3 ggrid(OUTW / BN, NROWS / BM);   // (16, 128)
    gemm_act<0,1><<<ggrid, NTHREADS, SMEM_TOTAL>>>(A0, B + 0 * WSTRIDE, WS + 0 * OUTW, AS,
                                                   b0, a0, scale, nullptr, A1, nullptr);
    gemm_act<0,0><<<ggrid, NTHREADS, SMEM_TOTAL>>>(A1, B + 1 * WSTRIDE, WS + 1 * OUTW, AS,
                                                   b1, a1, scale, nullptr, A0, nullptr);
    gemm_act<1,0><<<ggrid, NTHREADS, SMEM_TOTAL>>>(A0, B + 2 * WSTRIDE, WS + 2 * OUTW, AS,
                                                   b2, a2, scale, outb, nullptr, out);
}

// round 17
// speedup vs baseline: 1.0050x; 1.0050x over previous
#include <cuda_runtime.h>
#include <math.h>
#include <stdint.h>

// Problem constants:
//   X: [16384, 1024] fp32; per layer: wpn [2048,2048], b [2048], a [1024,9,1]
//   scale [1], out_bias [1024]; out [16384,1024] fp32
#define NROWS 16384
#define INW   1024
#define OUTW  2048
#define NG    1024

#define BM 128
#define BN 128
#define BK 128                 // int8 elements per chunk (128 bytes/row)
#define NCHUNK (INW / BK)      // 8
#define NTHREADS 256

// SMEM stage: A (128x128 s8 = 16KB) + B (128x128 s8 = 16KB)
#define OFF_A  0
#define OFF_B  16384
#define STAGE  32768
#define NSTAGE 3
#define SMEM_TOTAL (NSTAGE * STAGE)   // 98304 -> 2 CTAs/SM

// epilogue staging: [128 rows][64 cols] int8, stride 80 (16B-aligned, conflict-free)
#define STG_STRIDE 80

// -------- static device buffers (no allocation) --------
__device__ int8_t g_A0[(size_t)NROWS * INW];
__device__ int8_t g_A1[(size_t)NROWS * INW];
__device__ int8_t g_B[3][(size_t)OUTW * INW];
__device__ float  g_wscale[3][OUTW];   // per-output-channel |raw_w| max
__device__ float  g_ascale[NROWS];     // per-row |X| max

// -------- PTX helpers (legal on compute_100) --------
__device__ __forceinline__ uint32_t smem_u32(const void* p) {
    uint32_t a;
    asm("{ .reg .u64 t; cvta.to.shared.u64 t, %1; cvt.u32.u64 %0, t; }" : "=r"(a) : "l"(p));
    return a;
}
#define CP_ASYNC16(dst, src) \
    asm volatile("cp.async.cg.shared.global [%0], [%1], 16;" :: "r"(dst), "l"(src))
#define CP_COMMIT() asm volatile("cp.async.commit_group;" ::: "memory")
#define CP_WAIT1()  asm volatile("cp.async.wait_group 1;" ::: "memory")
#define CP_WAIT0()  asm volatile("cp.async.wait_group 0;" ::: "memory")

#define LDSM4(r0, r1, r2, r3, addr) \
    asm volatile("ldmatrix.sync.aligned.m8n8.x4.shared.b16 {%0,%1,%2,%3}, [%4];" \
                 : "=r"(r0), "=r"(r1), "=r"(r2), "=r"(r3) : "r"(addr))

#define MMA_S8(d, a, b0, b1) \
    asm volatile("mma.sync.aligned.m16n8k32.row.col.s32.s8.s8.s32 " \
                 "{%0,%1,%2,%3},{%4,%5,%6,%7},{%8,%9},{%0,%1,%2,%3};" \
                 : "+r"((d)[0]), "+r"((d)[1]), "+r"((d)[2]), "+r"((d)[3]) \
                 : "r"((a)[0]), "r"((a)[1]), "r"((a)[2]), "r"((a)[3]), "r"(b0), "r"(b1))

__device__ __forceinline__ int q8(float v, float qs) {
    int q = __float2int_rn(v * qs);
    return max(-127, min(127, q));
}

// -------- fused prep kernels (single pass, localized scales) --------

// One warp per row: row absmax + quantize in one read. 8 rows/CTA.
__global__ void prep_x(const float* __restrict__ X, int8_t* __restrict__ A,
                       float* __restrict__ ascale)
{
    const int row  = blockIdx.x * 8 + (threadIdx.x >> 5);
    const int lane = threadIdx.x & 31;
    const float* xr = X + (size_t)row * INW;

    float4 v[8];
    #pragma unroll
    for (int q = 0; q < 4; q++) v[q]     = *(const float4*)(xr + lane * 16 + q * 4);
    #pragma unroll
    for (int q = 0; q < 4; q++) v[4 + q] = *(const float4*)(xr + 512 + lane * 16 + q * 4);

    float m = 0.f;
    #pragma unroll
    for (int q = 0; q < 8; q++)
        m = fmaxf(m, fmaxf(fmaxf(fabsf(v[q].x), fabsf(v[q].y)),
                           fmaxf(fabsf(v[q].z), fabsf(v[q].w))));
    #pragma unroll
    for (int o = 16; o > 0; o >>= 1) m = fmaxf(m, __shfl_xor_sync(0xFFFFFFFF, m, o));
    const float rm = fmaxf(m, 1e-20f);
    const float qs = 127.f / rm;

    uint32_t pk[8];
    #pragma unroll
    for (int q = 0; q < 8; q++)
        pk[q] = (uint32_t)(q8(v[q].x, qs) & 0xFF)
              | ((uint32_t)(q8(v[q].y, qs) & 0xFF) << 8)
              | ((uint32_t)(q8(v[q].z, qs) & 0xFF) << 16)
              | ((uint32_t)(q8(v[q].w, qs) & 0xFF) << 24);
    int8_t* ar = A + (size_t)row * INW;
    *(uint4*)(ar + lane * 16)       = make_uint4(pk[0], pk[1], pk[2], pk[3]);
    *(uint4*)(ar + 512 + lane * 16) = make_uint4(pk[4], pk[5], pk[6], pk[7]);
    if (lane == 0) ascale[row] = rm;
}

// CTA owns 32 n-columns x full k. Phase 1: per-channel absmax (DRAM stream).
// Phase 2: re-read (L2-hot), quantize, transpose to Bt[n][k], full-row stores.
__global__ void prep_wf(const float* __restrict__ w0p, const float* __restrict__ w1p,
                        const float* __restrict__ w2p, int8_t* __restrict__ Bbase,
                        float* __restrict__ wsbase)
{
    __shared__ float s[128][33];
    __shared__ float red[8][32];
    __shared__ float wss[32];
    const int layer = blockIdx.y;
    const float* wpn = (layer == 0) ? w0p : (layer == 1) ? w1p : w2p;
    int8_t* B = Bbase + (size_t)layer * OUTW * INW;
    float* ws = wsbase + (size_t)layer * OUTW;
    const int n0 = blockIdx.x * 32;
    const int t = threadIdx.x;          // 256
    const int nl = t & 31, kk = t >> 5; // 32 n x 8 k-lanes

    // phase 1: per-channel absmax
    float m = 0.f;
    for (int k = kk; k < INW; k += 8) {
        float d = wpn[(size_t)k * OUTW + n0 + nl] - wpn[(size_t)(k + INW) * OUTW + n0 + nl];
        m = fmaxf(m, fabsf(d));
    }
    red[kk][nl] = m;
    __syncthreads();
    if (t < 32) {
        float mm = red[0][t];
        #pragma unroll
        for (int i = 1; i < 8; i++) mm = fmaxf(mm, red[i][t]);
        mm = fmaxf(mm, 1e-20f);
        wss[t] = 127.f / mm;
        ws[n0 + t] = mm;
    }
    __syncthreads();

    // phase 2: quantize + transpose, 128-k tiles
    for (int kt = 0; kt < INW; kt += 128) {
        #pragma unroll
        for (int i = 0; i < 16; i++) {
            int k = kt + kk + i * 8;
            s[kk + i * 8][nl] = wpn[(size_t)k * OUTW + n0 + nl]
                              - wpn[(size_t)(k + INW) * OUTW + n0 + nl];
        }
        __syncthreads();
        const int n = t >> 3, seg = t & 7;
        const float qs = wss[n];
        uint32_t pk[4];
        #pragma unroll
        for (int q = 0; q < 4; q++) {
            uint32_t v = 0;
            #pragma unroll
            for (int j = 0; j < 4; j++)
                v |= (uint32_t)(q8(s[seg * 16 + q * 4 + j][n], qs) & 0xFF) << (8 * j);
            pk[q] = v;
        }
        *(uint4*)(B + (size_t)(n0 + n) * INW + kt + seg * 16) = make_uint4(pk[0], pk[1], pk[2], pk[3]);
        __syncthreads();
    }
}

// -------- fused GEMM(int8, mma.sync) + activation --------
__device__ __forceinline__ float act_eval(float x0, float x1, const float* __restrict__ av)
{
    x0 = fminf(fmaxf(x0, -1.f), 1.f);
    x1 = fminf(fmaxf(x1, -1.f), 1.f);
    const float lo0 = (x0 < 0.f) ? -1.f : 0.f;
    const float lo1 = (x1 < 0.f) ? -1.f : 0.f;
    const float f0 = x0 - lo0;
    const float f1 = x1 - lo1;
    const int base = ((x0 < 0.f) ? 0 : 1) + 3 * ((x1 < 0.f) ? 0 : 1);
    const float v00 = __ldg(av + base);
    const float v10 = __ldg(av + base + 1);
    const float v01 = __ldg(av + base + 3);
    const float v11 = __ldg(av + base + 4);
    return (1.f - f0) * ((1.f - f1) * v00 + f1 * v01)
         +        f0  * ((1.f - f1) * v10 + f1 * v11);
}

template<int LAST, int FIRST>
__global__ void __launch_bounds__(NTHREADS, 2)
gemm_act(const int8_t* __restrict__ A, const int8_t* __restrict__ B,
         const float* __restrict__ wscale, const float* __restrict__ ascale,
         const float* __restrict__ bias, const float* __restrict__ act,
         const float* __restrict__ scale_p, const float* __restrict__ out_bias,
         int8_t* __restrict__ Ynext, float* __restrict__ Yout)
{
    extern __shared__ __align__(1024) char smem[];
    const uint32_t sb = smem_u32(smem);
    const int tid  = threadIdx.x;
    const int wid  = tid >> 5;
    const int lane = tid & 31;
    const int rowBase = blockIdx.y * BM;
    const int nBase   = blockIdx.x * BN;
    const int warp_m = (wid & 1) * 64;        // {0, 64}
    const int warp_n = (wid >> 1) * 32;       // {0, 32, 64, 96}
    // warp-phase: desynchronize LDSM/MMA bursts across warps and across
    // co-resident CTAs (int accumulation is order-exact -> bit-identical result)
    const int phase = (wid + ((blockIdx.x & 1) << 1)) & 3;

    // ---- loader mapping: 256 thr; r0 = tid>>3 in 0..31, 16B segment ----
    const int r0   = tid >> 3;
    const int cseg = (tid & 7) * 16;
    const uint32_t swc = (uint32_t)cseg ^ ((uint32_t)(r0 & 7) * 16);
    uint32_t swOff[4];
    #pragma unroll
    for (int i = 0; i < 4; i++)
        swOff[i] = (uint32_t)(r0 + 32 * i) * 128 + swc;

    const char* gA = (const char*)(A + (size_t)(rowBase + r0) * INW) + cseg;
    const char* gB = (const char*)(B + (size_t)(nBase  + r0) * INW) + cseg;
    const size_t RSTRIDE = (size_t)32 * INW;   // 32 rows (1 byte/elem)

    const uint32_t swx  = (uint32_t)(lane & 7) * 16;
    const uint32_t rsel = (uint32_t)(lane & 15);
    const uint32_t csel = (uint32_t)(lane >> 4) * 16;

    int acc[4][4][4];
    #pragma unroll
    for (int a = 0; a < 4; a++)
        #pragma unroll
        for (int b = 0; b < 4; b++)
            #pragma unroll
            for (int q = 0; q < 4; q++) acc[a][b][q] = 0;

    // prologue: stages 0..1
    #pragma unroll
    for (int p = 0; p < 2; p++) {
        const uint32_t st = sb + p * STAGE;
        const size_t go = (size_t)p * 128;   // BK bytes along k
        #pragma unroll
        for (int i = 0; i < 4; i++) {
            CP_ASYNC16(st + OFF_A + swOff[i], gA + go + i * RSTRIDE);
            CP_ASYNC16(st + OFF_B + swOff[i], gB + go + i * RSTRIDE);
        }
        CP_COMMIT();
    }

    for (int c = 0; c < NCHUNK; c++) {
        if (c + 1 < NCHUNK) CP_WAIT1();
        else                CP_WAIT0();
        __syncthreads();   // stage c resident; all warps done reading stage (c-1)%3

        const uint32_t stc = sb + (c % NSTAGE) * STAGE;
        #pragma unroll
        for (int i = 0; i < 4; i++) {
            const int ks = (i + phase) & 3;
            const uint32_t col = ((uint32_t)ks * 32 + csel) ^ swx;
            uint32_t bh[2][4];
            #pragma unroll
            for (int pb = 0; pb < 2; pb++) {
                uint32_t ro = (uint32_t)(warp_n + pb * 16 + rsel) * 128 + col;
                LDSM4(bh[pb][0], bh[pb][1], bh[pb][2], bh[pb][3], stc + OFF_B + ro);
            }
            uint32_t afr[2][4];
            {
                uint32_t ro = (uint32_t)(warp_m + rsel) * 128 + col;
                LDSM4(afr[0][0], afr[0][1], afr[0][2], afr[0][3], stc + OFF_A + ro);
            }
            #pragma unroll
            for (int mb = 0; mb < 4; mb++) {
                const int cur = mb & 1, nxt = cur ^ 1;
                if (mb < 3) {
                    uint32_t ro = (uint32_t)(warp_m + (mb + 1) * 16 + rsel) * 128 + col;
                    LDSM4(afr[nxt][0], afr[nxt][1], afr[nxt][2], afr[nxt][3], stc + OFF_A + ro);
                }
                #pragma unroll
                for (int nb = 0; nb < 4; nb++) {
                    const int pb = nb >> 1, s = nb & 1;
                    MMA_S8(acc[mb][nb], afr[cur], bh[pb][s], bh[pb][s + 2]);
                }
            }
            // issue next-chunk prefetch AFTER the first ks-step, off the
            // post-barrier LDSM storm
            if (i == 0 && c + 2 < NCHUNK) {
                const uint32_t stn = sb + ((c + 2) % NSTAGE) * STAGE;
                const size_t go = (size_t)(c + 2) * 128;
                #pragma unroll
                for (int j = 0; j < 4; j++) {
                    CP_ASYNC16(stn + OFF_A + swOff[j], gA + go + j * RSTRIDE);
                    CP_ASYNC16(stn + OFF_B + swOff[j], gB + go + j * RSTRIDE);
                }
                CP_COMMIT();
            }
        }
    }

    // ---- epilogue: per-row x per-channel dequant + bias + grid activation ----
    const float ls = cbrtf(fabsf(scale_p[0]));
    const float inv127 = 1.f / 127.f;
    const float lsq = ls * inv127;            // per-unit A scale (mid layers)
    const int gWarp = ((nBase + warp_n) >> 1);
    const int glWarp = (warp_n >> 1);   // CTA-local group offset (0,16,32,48)

    float aLo[4], aHi[4];
    #pragma unroll
    for (int mb = 0; mb < 4; mb++) {
        const int rlo = rowBase + warp_m + mb * 16 + (lane >> 2);
        aLo[mb] = FIRST ? ascale[rlo]     * lsq : lsq;
        aHi[mb] = FIRST ? ascale[rlo + 8] * lsq : lsq;
    }

    #pragma unroll
    for (int nb = 0; nb < 4; nb++) {
        const int g  = gWarp + nb * 4 + (lane & 3);
        const int c0 = 2 * g;
        const float2 wsv = *(const float2*)(wscale + c0);
        const float sB0 = wsv.x * inv127, sB1 = wsv.y * inv127;
        const float b0v = bias[c0], b1v = bias[c0 + 1];
        const float* av = act + (size_t)g * 9;
        const int gl = glWarp + nb * 4 + (lane & 3);
        #pragma unroll
        for (int mb = 0; mb < 4; mb++) {
            const int rl  = warp_m + mb * 16 + (lane >> 2);
            const int rlo = rowBase + rl;
            const int* d = acc[mb][nb];
            const float oLo = act_eval((float)d[0] * aLo[mb] * sB0 + b0v,
                                       (float)d[1] * aLo[mb] * sB1 + b1v, av);
            const float oHi = act_eval((float)d[2] * aHi[mb] * sB0 + b0v,
                                       (float)d[3] * aHi[mb] * sB1 + b1v, av);
            if (LAST) {
                const float ob = out_bias[g];
                Yout[(size_t)rlo * NG + g]       = oLo + ob;
                Yout[(size_t)(rlo + 8) * NG + g] = oHi + ob;
            } else {
                smem[rl * STG_STRIDE + gl]       = (char)(int8_t)q8(oLo, 127.f);
                smem[(rl + 8) * STG_STRIDE + gl] = (char)(int8_t)q8(oHi, 127.f);
            }
        }
    }
    if (!LAST) {
        __syncthreads();
        // coalesced copy-out: 128 rows x 64 bytes; thread -> 32B of one row
        const int r = tid >> 1, half = tid & 1;
        const char* src = smem + r * STG_STRIDE + half * 32;
        uint4 v0 = *(const uint4*)src;
        uint4 v1 = *(const uint4*)(src + 16);
        int8_t* dst = Ynext + (size_t)(rowBase + r) * NG + (nBase >> 1) + half * 32;
        *(uint4*)dst        = v0;
        *(uint4*)(dst + 16) = v1;
    }
}

extern "C" void kernel_launch(void* const* d_in, const int* in_sizes, int n_in,
                              void* d_out, int out_size)
{
    (void)in_sizes; (void)n_in; (void)out_size;
    const float* X     = (const float*)d_in[0];
    const float* w0    = (const float*)d_in[1];
    const float* b0    = (const float*)d_in[2];
    const float* a0    = (const float*)d_in[3];
    const float* w1    = (const float*)d_in[4];
    const float* b1    = (const float*)d_in[5];
    const float* a1    = (const float*)d_in[6];
    const float* w2    = (const float*)d_in[7];
    const float* b2    = (const float*)d_in[8];
    const float* a2    = (const float*)d_in[9];
    const float* scale = (const float*)d_in[10];
    const float* outb  = (const float*)d_in[11];
    float* out = (float*)d_out;

    int8_t *A0, *A1, *B;
    float *WS, *AS;
    cudaGetSymbolAddress((void**)&A0, g_A0);
    cudaGetSymbolAddress((void**)&A1, g_A1);
    cudaGetSymbolAddress((void**)&B,  g_B);
    cudaGetSymbolAddress((void**)&WS, g_wscale);
    cudaGetSymbolAddress((void**)&AS, g_ascale);
    const size_t WSTRIDE = (size_t)OUTW * INW;

    cudaFuncSetAttribute(gemm_act<0,1>, cudaFuncAttributeMaxDynamicSharedMemorySize, SMEM_TOTAL);
    cudaFuncSetAttribute(gemm_act<0,0>, cudaFuncAttributeMaxDynamicSharedMemorySize, SMEM_TOTAL);
    cudaFuncSetAttribute(gemm_act<1,0>, cudaFuncAttributeMaxDynamicSharedMemorySize, SMEM_TOTAL);

    // fused prep (single pass each)
    prep_x<<<NROWS / 8, 256>>>(X, A0, AS);
    prep_wf<<<dim3(OUTW / 32, 3), 256>>>(w0, w1, w2, B, WS);

    dim3 ggrid(OUTW / BN, NROWS / BM);   // (16, 128)
    gemm_act<0,1><<<ggrid, NTHREADS, SMEM_TOTAL>>>(A0, B + 0 * WSTRIDE, WS + 0 * OUTW, AS,
                                                   b0, a0, scale, nullptr, A1, nullptr);
    gemm_act<0,0><<<ggrid, NTHREADS, SMEM_TOTAL>>>(A1, B + 1 * WSTRIDE, WS + 1 * OUTW, AS,
                                                   b1, a1, scale, nullptr, A0, nullptr);
    gemm_act<1,0><<<ggrid, NTHREADS, SMEM_TOTAL>>>(A0, B + 2 * WSTRIDE, WS + 2 * OUTW, AS,
                                                   b2, a2, scale, outb, nullptr, out);
}